// round 16
// baseline (speedup 1.0000x reference)
#include <cuda_runtime.h>
#include <cstdint>

// Problem dims (fixed by the dataset's setup_inputs)
#define C_   128
#define H_   56
#define W_   56
#define HW_  3136
#define TOTAL_ (16 * 128 * 3136)

#define TPB     448                 // 32 row-pair segments of 14 threads
#define OCT_BC  392                 // 8-px tiles per (b,c)
#define PX_BLK  3584                // pixels per block (448*8), contiguous
#define NBLOCKS (TOTAL_ / PX_BLK)   // 1792

// set.ge -> -1 (true) / 0 (false): single SASS FSET, no predication
__device__ __forceinline__ int setge(float a, float b) {
    int r;
    asm("set.ge.s32.f32 %0, %1, %2;" : "=r"(r) : "f"(a), "f"(b));
    return r;
}

// ---- nibble-packed rank counters, 8 windows (2 window-rows x 4 cols) -------
// Tile cells (r, c): r in 0..3, c in 0..5. Window (wr, wc): rows wr..wr+2,
// cols wc..wc+2; element e = 3*(r-wr) + (c-wc); win = wr*4+wc (0..7).
// Counter id = win*9 + e (0..71) -> nibble id&7 of word id>>3 (9 words).
// Init = 8 - e; per-window prefix stays in [0,8] (decrements bounded by
// #later elements, increments by #earlier) -> nibbles never carry/borrow,
// so whole-word add of packed signed constants is exact (SWAR).
__host__ __device__ constexpr int vid(int wr, int wc, int r, int c) {
    return (wr * 4 + wc) * 9 + 3 * (r - wr) + (c - wc);
}
__host__ __device__ constexpr int nib(int wi, int id) {
    return ((id >> 3) == wi) ? (1 << (4 * (id & 7))) : 0;
}
__host__ __device__ constexpr int kpair(int wi, int rX, int cX, int rY, int cY) {
    int s = 0;
    for (int wr = 0; wr < 2; wr++)
        for (int wc = 0; wc < 4; wc++)
            if (rX >= wr && rX <= wr + 2 && rY >= wr && rY <= wr + 2 &&
                cX >= wc && cX <= wc + 2 && cY >= wc && cY <= wc + 2)
                s += nib(wi, vid(wr, wc, rX, cX)) - nib(wi, vid(wr, wc, rY, cY));
    return s;
}
__host__ __device__ constexpr int initw(int wi) {
    int v = 0;
    for (int id = wi * 8; id < wi * 8 + 8; id++)
        v |= (8 - (id % 9)) << (4 * (id & 7));
    return v;
}

#define PAIR(rX, cX, rY, cY)                                                  \
    {                                                                         \
        const int m = setge(v[rX][cX], v[rY][cY]);                            \
        { constexpr int K = kpair(0, rX, cX, rY, cY); if (K) w0 += m * K; }   \
        { constexpr int K = kpair(1, rX, cX, rY, cY); if (K) w1 += m * K; }   \
        { constexpr int K = kpair(2, rX, cX, rY, cY); if (K) w2 += m * K; }   \
        { constexpr int K = kpair(3, rX, cX, rY, cY); if (K) w3 += m * K; }   \
        { constexpr int K = kpair(4, rX, cX, rY, cY); if (K) w4 += m * K; }   \
        { constexpr int K = kpair(5, rX, cX, rY, cY); if (K) w5 += m * K; }   \
        { constexpr int K = kpair(6, rX, cX, rY, cY); if (K) w6 += m * K; }   \
        { constexpr int K = kpair(7, rX, cX, rY, cY); if (K) w7 += m * K; }   \
        { constexpr int K = kpair(8, rX, cX, rY, cY); if (K) w8 += m * K; }   \
    }

// within-row co-windowed pairs (|dc| <= 2), 9 per row
#define WROWV(r)                                                              \
    PAIR(r,0,r,1) PAIR(r,0,r,2) PAIR(r,1,r,2) PAIR(r,1,r,3) PAIR(r,2,r,3)     \
    PAIR(r,2,r,4) PAIR(r,3,r,4) PAIR(r,3,r,5) PAIR(r,4,r,5)
// cross-row pairs (|dc| <= 2), 24 per row pair
#define XROWV(ra, rb)                                                         \
    PAIR(ra,0,rb,0) PAIR(ra,0,rb,1) PAIR(ra,0,rb,2)                           \
    PAIR(ra,1,rb,0) PAIR(ra,1,rb,1) PAIR(ra,1,rb,2) PAIR(ra,1,rb,3)           \
    PAIR(ra,2,rb,0) PAIR(ra,2,rb,1) PAIR(ra,2,rb,2) PAIR(ra,2,rb,3)           \
    PAIR(ra,2,rb,4)                                                           \
    PAIR(ra,3,rb,1) PAIR(ra,3,rb,2) PAIR(ra,3,rb,3) PAIR(ra,3,rb,4)           \
    PAIR(ra,3,rb,5)                                                           \
    PAIR(ra,4,rb,2) PAIR(ra,4,rb,3) PAIR(ra,4,rb,4) PAIR(ra,4,rb,5)           \
    PAIR(ra,5,rb,3) PAIR(ra,5,rb,4) PAIR(ra,5,rb,5)

// rank extraction — win/e literals after expansion; selector folds
#define WSEL_(i) ((i)==0?w0:(i)==1?w1:(i)==2?w2:(i)==3?w3:(i)==4?w4:            \
                  (i)==5?w5:(i)==6?w6:(i)==7?w7:w8)
#define RANK_(win, e) ((WSEL_((((win)*9+(e)) >> 3)) >> (4 * (((win)*9+(e)) & 7))) & 15)

// one window: value accumulate + byte index scatter (wr, wc literals)
#define DOWIN(wr, wc, stp, out)                                                  \
    {                                                                            \
        float acc = 0.f;                                                         \
        int q;                                                                   \
        q = RANK_((wr)*4+(wc),0); acc = fmaf(v[(wr)+0][(wc)+0], tb[q], acc); (stp)[9*(wc)+q] = 0; \
        q = RANK_((wr)*4+(wc),1); acc = fmaf(v[(wr)+0][(wc)+1], tb[q], acc); (stp)[9*(wc)+q] = 1; \
        q = RANK_((wr)*4+(wc),2); acc = fmaf(v[(wr)+0][(wc)+2], tb[q], acc); (stp)[9*(wc)+q] = 2; \
        q = RANK_((wr)*4+(wc),3); acc = fmaf(v[(wr)+1][(wc)+0], tb[q], acc); (stp)[9*(wc)+q] = 3; \
        q = RANK_((wr)*4+(wc),4); acc = fmaf(v[(wr)+1][(wc)+1], tb[q], acc); (stp)[9*(wc)+q] = 4; \
        q = RANK_((wr)*4+(wc),5); acc = fmaf(v[(wr)+1][(wc)+2], tb[q], acc); (stp)[9*(wc)+q] = 5; \
        q = RANK_((wr)*4+(wc),6); acc = fmaf(v[(wr)+2][(wc)+0], tb[q], acc); (stp)[9*(wc)+q] = 6; \
        q = RANK_((wr)*4+(wc),7); acc = fmaf(v[(wr)+2][(wc)+1], tb[q], acc); (stp)[9*(wc)+q] = 7; \
        q = RANK_((wr)*4+(wc),8); acc = fmaf(v[(wr)+2][(wc)+2], tb[q], acc); (stp)[9*(wc)+q] = 8; \
        out = acc;                                                               \
    }

__global__ __launch_bounds__(TPB, 3)   // 48-reg budget, occ 65.6% (R14's point)
void rrsvm_kernel(const float* __restrict__ x,
                  const float* __restrict__ s,
                  float* __restrict__ vout,
                  float* __restrict__ idxout)
{
    __shared__ float ssm[14][18];                        // 2 channels per warp
    __shared__ __align__(16) unsigned char stage8[TPB * 72];  // block byte stage

    const int i    = threadIdx.x;
    const int warp = i >> 5;
    const int lane = i & 31;

    const int u  = blockIdx.x * TPB + i;     // tile id, exact grid
    const int bc = u / OCT_BC;               // b*C + c
    const int q_ = u - bc * OCT_BC;
    const int yp = q_ / 14;
    const int xu = q_ - yp * 14;             // == i % 14 (448, 392 mult of 14)
    const int y  = 2 * yp;                   // top output row of the 2x4 tile
    const int xx = 4 * xu;

    // Warp can straddle at most one (b,c) boundary: two-channel s table.
    const int bcf = __shfl_sync(0xFFFFFFFFu, bc, 0);
    const int bcl = __shfl_sync(0xFFFFFFFFu, bc, 31);
    if (lane < 9)
        ssm[warp][lane] = __ldg(s + (bcf & (C_ - 1)) * 9 + lane);
    else if (lane < 18)
        ssm[warp][lane] = __ldg(s + (bcl & (C_ - 1)) * 9 + lane - 9);
    __syncwarp();
    const float* tb = ssm[warp] + ((bc != bcf) ? 9 : 0);

    const float* __restrict__ xb = x + (size_t)bc * HW_;

    // 4 rows x 6 cols covering the 8 windows. Interior 4 cols via float4;
    // edges from neighbor lanes' float4 (xu==0 / xu==13 are true image
    // borders -> padding zero; only warp-boundary lanes need fixup loads).
    float v[4][6];
#pragma unroll
    for (int rr = 0; rr < 4; rr++) {
        const int gy   = y + rr - 1;
        const bool rok = ((unsigned)gy < (unsigned)H_);
        const float* p = xb + gy * W_ + xx;
        float4 m4 = make_float4(0.f, 0.f, 0.f, 0.f);
        if (rok) m4 = *(const float4*)p;                 // 16B aligned
        v[rr][1] = m4.x; v[rr][2] = m4.y; v[rr][3] = m4.z; v[rr][4] = m4.w;

        float left  = __shfl_up_sync(0xFFFFFFFFu, m4.w, 1);
        float right = __shfl_down_sync(0xFFFFFFFFu, m4.x, 1);
        if (lane == 0  && xu != 0)  left  = rok ? __ldg(p - 1) : 0.f;
        if (lane == 31 && xu != 13) right = rok ? __ldg(p + 4) : 0.f;
        v[rr][0] = (xu == 0)  ? 0.f : left;
        v[rr][5] = (xu == 13) ? 0.f : right;
    }

    // nibble-packed rank accumulation, 72 counters in 9 words
    int w0 = initw(0), w1 = initw(1), w2 = initw(2), w3 = initw(3), w4 = initw(4);
    int w5 = initw(5), w6 = initw(6), w7 = initw(7), w8 = initw(8);

    WROWV(0) WROWV(1) WROWV(2) WROWV(3)
    XROWV(0, 1) XROWV(1, 2) XROWV(2, 3)     // adjacent rows
    XROWV(0, 2) XROWV(1, 3)                 // distance-2 rows

    // Stage bases: block's 3584 px are globally contiguous; this tile's two
    // 4-px runs sit at (pA - P0)*9 and +504 bytes in the block stage.
    const size_t pA  = (size_t)bc * HW_ + (size_t)y * W_ + xx;
    const int    off = (int)(pA - (size_t)blockIdx.x * PX_BLK);
    unsigned char* stA = stage8 + off * 9;
    unsigned char* stB = stA + 504;          // row y+1 = +56 px

    float a00, a01, a02, a03, a10, a11, a12, a13;
    DOWIN(0, 0, stA, a00) DOWIN(0, 1, stA, a01)
    DOWIN(0, 2, stA, a02) DOWIN(0, 3, stA, a03)
    DOWIN(1, 0, stB, a10) DOWIN(1, 1, stB, a11)
    DOWIN(1, 2, stB, a12) DOWIN(1, 3, stB, a13)

    if (vout) {
        *(float4*)(vout + pA)       = make_float4(a00, a01, a02, a03);
        *(float4*)(vout + pA + W_)  = make_float4(a10, a11, a12, a13);
    }

    __syncthreads();                         // single terminal barrier

    if (idxout) {
        // Block's 3584 px = 32256 idx floats, staged as 32256 bytes = 8064 u32.
        // Each u32 -> float4 via PRMT(0x4B0000|e) + FADD(-8388608): exact for
        // e in 0..8 (verified round 9). Linear, fully coalesced.
        const unsigned* sw  = (const unsigned*)stage8;
        float4* dst = (float4*)(idxout + (size_t)blockIdx.x * (PX_BLK * 9));
#pragma unroll
        for (int k = 0; k < 18; k++) {
            const int m = i + TPB * k;
            const unsigned w = sw[m];
            float4 f;
            f.x = __uint_as_float(__byte_perm(w, 0x4B000000u, 0x7440)) - 8388608.f;
            f.y = __uint_as_float(__byte_perm(w, 0x4B000000u, 0x7441)) - 8388608.f;
            f.z = __uint_as_float(__byte_perm(w, 0x4B000000u, 0x7442)) - 8388608.f;
            f.w = __uint_as_float(__byte_perm(w, 0x4B000000u, 0x7443)) - 8388608.f;
            dst[m] = f;
        }
    }
}

extern "C" void kernel_launch(void* const* d_in, const int* in_sizes, int n_in,
                              void* d_out, int out_size) {
    const float* x = (const float*)d_in[0];
    const float* s = (const float*)d_in[1];

    float* vout   = (float*)d_out;
    float* idxout = nullptr;

    // Reference returns (out[B,C,H,W], indices[B,C,H,W,9]); harness concatenates.
    if (out_size >= 10 * TOTAL_) {
        idxout = (float*)d_out + TOTAL_;   // [out | indices]
    } else if (out_size == 9 * TOTAL_) {
        idxout = (float*)d_out;            // indices only
        vout   = nullptr;
    }

    rrsvm_kernel<<<NBLOCKS, TPB>>>(x, s, vout, idxout);
}

// round 17
// speedup vs baseline: 1.3096x; 1.3096x over previous
#include <cuda_runtime.h>
#include <cstdint>

// Problem dims (fixed by the dataset's setup_inputs)
#define C_   128
#define H_   56
#define W_   56
#define HW_  3136
#define TOTAL_ (16 * 128 * 3136)

#define NQUAD_TOT (TOTAL_ / 4)    // 1,605,632 quads (4 horizontal px each)
#define TPB 256

// set.ge -> -1 (true) / 0 (false): single SASS FSET, no predication
__device__ __forceinline__ int setge(float a, float b) {
    int r;
    asm("set.ge.s32.f32 %0, %1, %2;" : "=r"(r) : "f"(a), "f"(b));
    return r;
}

// ---- CELL-grouped nibble-packed rank counters, 4 windows -------------------
// Tile cells (r, c): r in 0..2, c in 0..5. Window w (0..3) = cols w..w+2;
// element e = 3r + (c - w). Each cell has one counter per window containing
// it (counts per col: 1,2,3,3,2,1). ALL of a cell's counters live in ONE
// word, so any pair (X, Y) updates at most word(X) and word(Y): <=2 IMADs.
//   word L_r = r   : cells (r,0),(r,1),(r,2)  offsets {0},{1+w},{3+w}
//   word R_r = 3+r : cells (r,3),(r,4),(r,5)  offsets {w-1},{3+(w-2)},{5}
// 6 words x 6 nibbles. Init = 8 - e; every per-window prefix stays in [0,8]
// (decrements bounded by #later elements, increments by #earlier), so
// nibbles never carry/borrow and whole-word adds of packed constants are
// exact (SWAR).
__host__ __device__ constexpr int wordof(int r, int c) { return r + (c < 3 ? 0 : 3); }
__host__ __device__ constexpr int noff(int r, int c, int w) {
    return (c == 0) ? 0
         : (c == 1) ? 1 + w
         : (c == 2) ? 3 + w
         : (c == 3) ? w - 1
         : (c == 4) ? 3 + (w - 2)
         :            5;
}
__host__ __device__ constexpr int kpair(int wi, int rX, int cX, int rY, int cY) {
    int s = 0;
    for (int w = 0; w < 4; w++) {
        const bool inX = (cX >= w && cX <= w + 2);
        const bool inY = (cY >= w && cY <= w + 2);
        if (inX && inY) {
            if (wordof(rX, cX) == wi) s += 1 << (4 * noff(rX, cX, w));
            if (wordof(rY, cY) == wi) s -= 1 << (4 * noff(rY, cY, w));
        }
    }
    return s;
}
__host__ __device__ constexpr int initw(int wi) {
    int v = 0;
    for (int r = 0; r < 3; r++)
        for (int c = 0; c < 6; c++)
            for (int w = 0; w < 4; w++)
                if (c >= w && c <= w + 2 && wordof(r, c) == wi)
                    v |= (8 - (3 * r + c - w)) << (4 * noff(r, c, w));
    return v;
}

#define PAIR(rX, cX, rY, cY)                                                  \
    {                                                                         \
        const int m = setge(v[rX][cX], v[rY][cY]);                            \
        { constexpr int K = kpair(0, rX, cX, rY, cY); if (K) u0 += m * K; }   \
        { constexpr int K = kpair(1, rX, cX, rY, cY); if (K) u1 += m * K; }   \
        { constexpr int K = kpair(2, rX, cX, rY, cY); if (K) u2 += m * K; }   \
        { constexpr int K = kpair(3, rX, cX, rY, cY); if (K) u3 += m * K; }   \
        { constexpr int K = kpair(4, rX, cX, rY, cY); if (K) u4 += m * K; }   \
        { constexpr int K = kpair(5, rX, cX, rY, cY); if (K) u5 += m * K; }   \
    }

// within-row co-windowed pairs (|dc| <= 2)
#define WROW(r)                                                               \
    PAIR(r,0,r,1) PAIR(r,0,r,2) PAIR(r,1,r,2) PAIR(r,1,r,3) PAIR(r,2,r,3)     \
    PAIR(r,2,r,4) PAIR(r,3,r,4) PAIR(r,3,r,5) PAIR(r,4,r,5)
// cross-row pairs, all col combos with |dc| <= 2
#define XROW(ra, rb)                                                          \
    PAIR(ra,0,rb,0) PAIR(ra,0,rb,1) PAIR(ra,0,rb,2)                           \
    PAIR(ra,1,rb,0) PAIR(ra,1,rb,1) PAIR(ra,1,rb,2) PAIR(ra,1,rb,3)           \
    PAIR(ra,2,rb,0) PAIR(ra,2,rb,1) PAIR(ra,2,rb,2) PAIR(ra,2,rb,3)           \
    PAIR(ra,2,rb,4)                                                           \
    PAIR(ra,3,rb,1) PAIR(ra,3,rb,2) PAIR(ra,3,rb,3) PAIR(ra,3,rb,4)           \
    PAIR(ra,3,rb,5)                                                           \
    PAIR(ra,4,rb,2) PAIR(ra,4,rb,3) PAIR(ra,4,rb,4) PAIR(ra,4,rb,5)           \
    PAIR(ra,5,rb,3) PAIR(ra,5,rb,4) PAIR(ra,5,rb,5)

// rank extraction — (w,e) literal after unroll: word/offset fold to constants
#define USEL_(i) ((i)==0?u0:(i)==1?u1:(i)==2?u2:(i)==3?u3:(i)==4?u4:u5)
#define RANK_(w, e) \
    ((USEL_(wordof((e)/3, (e)%3 + (w))) >> (4 * noff((e)/3, (e)%3 + (w), (w)))) & 15)

// one window: value accumulate + byte index scatter (w literal)
#define DOWIN(w, out)                                                            \
    {                                                                            \
        float acc = 0.f;                                                         \
        int q;                                                                   \
        q = RANK_(w,0); acc = fmaf(v[0][(w)+0], tb[q], acc); st[9*(w)+q] = 0;    \
        q = RANK_(w,1); acc = fmaf(v[0][(w)+1], tb[q], acc); st[9*(w)+q] = 1;    \
        q = RANK_(w,2); acc = fmaf(v[0][(w)+2], tb[q], acc); st[9*(w)+q] = 2;    \
        q = RANK_(w,3); acc = fmaf(v[1][(w)+0], tb[q], acc); st[9*(w)+q] = 3;    \
        q = RANK_(w,4); acc = fmaf(v[1][(w)+1], tb[q], acc); st[9*(w)+q] = 4;    \
        q = RANK_(w,5); acc = fmaf(v[1][(w)+2], tb[q], acc); st[9*(w)+q] = 5;    \
        q = RANK_(w,6); acc = fmaf(v[2][(w)+0], tb[q], acc); st[9*(w)+q] = 6;    \
        q = RANK_(w,7); acc = fmaf(v[2][(w)+1], tb[q], acc); st[9*(w)+q] = 7;    \
        q = RANK_(w,8); acc = fmaf(v[2][(w)+2], tb[q], acc); st[9*(w)+q] = 8;    \
        out = acc;                                                               \
    }

__global__ __launch_bounds__(TPB, 7)   // 36-reg target (R15's proven point)
void rrsvm_kernel(const float* __restrict__ x,
                  const float* __restrict__ s,
                  float* __restrict__ vout,
                  float* __restrict__ idxout)
{
    __shared__ float ssm[8][18];                             // 2 channels per warp
    __shared__ __align__(16) unsigned char stage8[8][1152];  // byte idx stage

    const int tid  = threadIdx.x;
    const int warp = tid >> 5;
    const int lane = tid & 31;
    const int t    = blockIdx.x * TPB + tid;            // quad id, exact grid

    const int p0  = t * 4;                              // first pixel (global)
    const int bc  = p0 / HW_;                           // b*C + c (4 | HW_)
    const int rem = p0 - bc * HW_;
    const int y   = rem / W_;
    const int xx  = rem - y * W_;                       // multiple of 4

    // Warp can straddle at most one (b,c) boundary: two-channel s table.
    const int bcf = __shfl_sync(0xFFFFFFFFu, bc, 0);
    const int bcl = __shfl_sync(0xFFFFFFFFu, bc, 31);
    if (lane < 9)
        ssm[warp][lane] = __ldg(s + (bcf & (C_ - 1)) * 9 + lane);
    else if (lane < 18)
        ssm[warp][lane] = __ldg(s + (bcl & (C_ - 1)) * 9 + lane - 9);
    __syncwarp();
    const float* tb = ssm[warp] + ((bc != bcf) ? 9 : 0);

    const float* __restrict__ xb = x + (size_t)bc * HW_;

    // 3 rows x 6 cols covering the 4 windows. Interior 4 via one float4;
    // edges come from the horizontally-adjacent lane's float4 (same row,
    // same channel whenever xx>0 / xx<52 — padding zeros propagate because
    // m4 is zeroed for OOB rows). Only warp-boundary lanes do fixup loads.
    float v[3][6];
#pragma unroll
    for (int rr = 0; rr < 3; rr++) {
        const int gy   = y + rr - 1;
        const bool rok = ((unsigned)gy < (unsigned)H_);
        const float* p = xb + gy * W_ + xx;
        float4 m4 = make_float4(0.f, 0.f, 0.f, 0.f);
        if (rok) m4 = *(const float4*)p;                 // 16B aligned
        v[rr][1] = m4.x; v[rr][2] = m4.y; v[rr][3] = m4.z; v[rr][4] = m4.w;

        float left  = __shfl_up_sync(0xFFFFFFFFu, m4.w, 1);
        float right = __shfl_down_sync(0xFFFFFFFFu, m4.x, 1);
        if (lane == 0  && xx > 0)  left  = rok ? __ldg(p - 1) : 0.f;
        if (lane == 31 && xx < 52) right = rok ? __ldg(p + 4) : 0.f;
        v[rr][0] = (xx == 0)  ? 0.f : left;
        v[rr][5] = (xx == 52) ? 0.f : right;
    }

    // cell-grouped nibble rank accumulation (6 words)
    int u0 = initw(0), u1 = initw(1), u2 = initw(2);
    int u3 = initw(3), u4 = initw(4), u5 = initw(5);

    WROW(0) WROW(1) WROW(2)
    XROW(0, 1) XROW(0, 2) XROW(1, 2)

    // Values (s-gather: <=9 distinct words in distinct banks -> multicast,
    // conflict-free) + byte index scatter (36B/lane regions -> lanes occupy
    // disjoint 9-word spans, near-conflict-free).
    unsigned char* st = &stage8[warp][lane * 36];
    float a0, a1, a2, a3;
    DOWIN(0, a0)
    DOWIN(1, a1)
    DOWIN(2, a2)
    DOWIN(3, a3)

    if (vout) {
        float4 o = make_float4(a0, a1, a2, a3);
        *(float4*)(vout + (size_t)p0) = o;               // 16B aligned
    }

    __syncwarp();
    if (idxout) {
        // warp's 128 pixels = 1152 idx floats, staged as 1152 bytes = 288 u32.
        // Each u32 -> float4 via PRMT(0x4B0000|e) + FADD(-8388608): exact for
        // e in 0..8 (verified round 9). 9 conflict-free LDS.32 per lane.
        const unsigned* sw  = (const unsigned*)stage8[warp];
        float4*         dst = (float4*)(idxout + (size_t)(t - lane) * 36);
#pragma unroll
        for (int k = 0; k < 9; k++) {
            const int m = lane + 32 * k;
            const unsigned w = sw[m];
            float4 f;
            f.x = __uint_as_float(__byte_perm(w, 0x4B000000u, 0x7440)) - 8388608.f;
            f.y = __uint_as_float(__byte_perm(w, 0x4B000000u, 0x7441)) - 8388608.f;
            f.z = __uint_as_float(__byte_perm(w, 0x4B000000u, 0x7442)) - 8388608.f;
            f.w = __uint_as_float(__byte_perm(w, 0x4B000000u, 0x7443)) - 8388608.f;
            dst[m] = f;
        }
    }
}

extern "C" void kernel_launch(void* const* d_in, const int* in_sizes, int n_in,
                              void* d_out, int out_size) {
    const float* x = (const float*)d_in[0];
    const float* s = (const float*)d_in[1];

    float* vout   = (float*)d_out;
    float* idxout = nullptr;

    // Reference returns (out[B,C,H,W], indices[B,C,H,W,9]); harness concatenates.
    if (out_size >= 10 * TOTAL_) {
        idxout = (float*)d_out + TOTAL_;   // [out | indices]
    } else if (out_size == 9 * TOTAL_) {
        idxout = (float*)d_out;            // indices only
        vout   = nullptr;
    }

    const int blocks = NQUAD_TOT / TPB;    // exact: 6272
    rrsvm_kernel<<<blocks, TPB>>>(x, s, vout, idxout);
}